// round 16
// baseline (speedup 1.0000x reference)
#include <cuda_runtime.h>
#include <cuda_bf16.h>

#define BATCH 256
#define SDIM  1024
#define NOFF  36
#define FP_SCALE 131072.0f      // 2^17

// Packed accumulator: [63:54] CTA arrivals, [53:14] fixed-point sum, [13:0] count.
__device__ unsigned long long gPack;   // zero-initialized; reset by last CTA each call

__global__ __launch_bounds__(32, 32)
void loss_39934605918651_kernel(const float* __restrict__ y_predict,
                                const int*   __restrict__ gt_pos,
                                float*       __restrict__ out) {
    const int b = blockIdx.x;
    const int t = threadIdx.x;

    // Each lane loads 8 gt pairs -> warp covers all 256 batches.
    const int2* g2 = (const int2*)gt_pos;
    int2 p[8];
    #pragma unroll
    for (int k = 0; k < 8; k++) p[k] = __ldg(&g2[t + 32 * k]);

    // Moment partials.
    int sx = 0, sy = 0, scc = 0;
    #pragma unroll
    for (int k = 0; k < 8; k++) {
        sx  += p[k].x;
        sy  += p[k].y;
        scc += p[k].x * p[k].x + p[k].y * p[k].y;
    }

    // This CTA's own gt position: predicated select of reg k = b>>5, then shuffle from lane b&31.
    const int kown = b >> 5;
    int gxl = p[0].x, gyl = p[0].y;
    #pragma unroll
    for (int k = 1; k < 8; k++) {
        if (kown == k) { gxl = p[k].x; gyl = p[k].y; }
    }
    const int gx = __shfl_sync(0xFFFFFFFFu, gxl, b & 31);
    const int gy = __shfl_sync(0xFFFFFFFFu, gyl, b & 31);

    // Warp-wide exact moment sums (single REDUX each).
    const int Sx = __reduce_add_sync(0xFFFFFFFFu, sx);
    const int Sy = __reduce_add_sync(0xFFFFFFFFu, sy);
    const int Sc = __reduce_add_sync(0xFFFFFFFFu, scc);

    // Closed-form valid count: in-bounds rows x cols of the 6x6 window.
    const int rows = min(gx + 2, SDIM - 1) - max(gx - 3, 0) + 1;
    const int cols = min(gy + 2, SDIM - 1) - max(gy - 3, 0) + 1;
    const int cnt  = rows * cols;

    int fpsum = 0;

    #pragma unroll
    for (int i = t; i < NOFF; i += 32) {
        const int q  = i / 6;
        const int oi = q - 3;
        const int oj = i - q * 6 - 3;
        const int px = gx + oi;
        const int py = gy + oj;

        const bool valid = (px >= 0) & (px < SDIM) & (py >= 0) & (py < SDIM);
        const int pcx = min(max(px, 0), SDIM - 1);
        const int pcy = min(max(py, 0), SDIM - 1);

        const float y_hat = __ldg(&y_predict[((size_t)b << 20) + ((size_t)pcx << 10) + pcy]);

        // sq = B*(px^2+py^2) - 2*(px*Sx + py*Sy) + Sc, exact in int32.
        const int   sq_i = BATCH * (px * px + py * py) - 2 * (px * Sx + py * Sy) + Sc;
        const float sq   = (float)sq_i;
        const float y    = __expf(-sq * 0.2f);   // underflows to 0 exactly like fp32 ref
        const float d    = y_hat - y;
        float term;
        if (y == 1.0f) {
            term = -__logf(y_hat) * d * d;
        } else {
            const float omy = 1.0f - y;
            const float w2  = omy * omy;
            term = -__logf(1.0f - y_hat) * (w2 * w2) * d * d;
        }
        if (valid) fpsum += __float2int_rn(term * FP_SCALE);   // term >= 0
    }

    // Exact, order-independent warp reduction.
    fpsum = __reduce_add_sync(0xFFFFFFFFu, fpsum);

    if (t == 0) {
        const unsigned long long mine =
            (1ULL << 54) | ((unsigned long long)(unsigned int)fpsum << 14)
                         | (unsigned long long)cnt;
        const unsigned long long old = atomicAdd(&gPack, mine);
        if ((old >> 54) == (unsigned long long)(BATCH - 1)) {
            // All 255 other adds are complete at the LTS (their arrivals are in `old`),
            // and same-thread same-address ordering holds, so a plain store reset is safe
            // and avoids the ATOMG.EXCH round-trip on the retire path.
            *(volatile unsigned long long*)&gPack = 0ULL;

            const unsigned long long tot = old + mine;   // complete total, no readback
            const long long fp = (long long)((tot >> 14) & ((1ULL << 40) - 1));
            const int       c  = (int)(tot & 0x3FFFULL);
            // fp <= ~5.5e9 -> fp32 rel err ~6e-8; keeps fp64 off the retire path.
            out[0] = (float)fp * (1.0f / FP_SCALE) / (float)c;
        }
    }
}

extern "C" void kernel_launch(void* const* d_in, const int* in_sizes, int n_in,
                              void* d_out, int out_size) {
    const float* y_predict = (const float*)d_in[0];
    const int*   gt_pos    = (const int*)d_in[1];
    float*       out       = (float*)d_out;
    loss_39934605918651_kernel<<<BATCH, 32>>>(y_predict, gt_pos, out);
}

// round 17
// speedup vs baseline: 1.0386x; 1.0386x over previous
#include <cuda_runtime.h>
#include <cuda_bf16.h>

#define BATCH 256
#define SDIM  1024
#define NOFF  36
#define FP_SCALE 131072.0f      // 2^17

// Packed accumulator: [63:54] CTA arrivals, [53:14] fixed-point sum, [13:0] count.
__device__ unsigned long long gPack;   // zero-initialized; reset by last CTA each call

__global__ __launch_bounds__(32, 32)
void loss_39934605918651_kernel(const float* __restrict__ y_predict,
                                const int*   __restrict__ gt_pos,
                                float*       __restrict__ out) {
    const int b = blockIdx.x;
    const int t = threadIdx.x;

    // Each lane loads 8 gt pairs -> warp covers all 256 batches.
    const int2* g2 = (const int2*)gt_pos;
    int2 p[8];
    #pragma unroll
    for (int k = 0; k < 8; k++) p[k] = __ldg(&g2[t + 32 * k]);

    // Moment partials.
    int sx = 0, sy = 0, scc = 0;
    #pragma unroll
    for (int k = 0; k < 8; k++) {
        sx  += p[k].x;
        sy  += p[k].y;
        scc += p[k].x * p[k].x + p[k].y * p[k].y;
    }

    // This CTA's own gt position: predicated select of reg k = b>>5, then shuffle from lane b&31.
    const int kown = b >> 5;
    int gxl = p[0].x, gyl = p[0].y;
    #pragma unroll
    for (int k = 1; k < 8; k++) {
        if (kown == k) { gxl = p[k].x; gyl = p[k].y; }
    }
    const int gx = __shfl_sync(0xFFFFFFFFu, gxl, b & 31);
    const int gy = __shfl_sync(0xFFFFFFFFu, gyl, b & 31);

    // Warp-wide exact moment sums (single REDUX each).
    const int Sx = __reduce_add_sync(0xFFFFFFFFu, sx);
    const int Sy = __reduce_add_sync(0xFFFFFFFFu, sy);
    const int Sc = __reduce_add_sync(0xFFFFFFFFu, scc);

    // Closed-form valid count: in-bounds rows x cols of the 6x6 window.
    const int rows = min(gx + 2, SDIM - 1) - max(gx - 3, 0) + 1;
    const int cols = min(gy + 2, SDIM - 1) - max(gy - 3, 0) + 1;
    const int cnt  = rows * cols;

    int fpsum = 0;

    #pragma unroll
    for (int i = t; i < NOFF; i += 32) {
        const int q  = i / 6;
        const int oi = q - 3;
        const int oj = i - q * 6 - 3;
        const int px = gx + oi;
        const int py = gy + oj;

        const bool valid = (px >= 0) & (px < SDIM) & (py >= 0) & (py < SDIM);
        const int pcx = min(max(px, 0), SDIM - 1);
        const int pcy = min(max(py, 0), SDIM - 1);

        const float y_hat = __ldg(&y_predict[((size_t)b << 20) + ((size_t)pcx << 10) + pcy]);

        // sq = B*(px^2+py^2) - 2*(px*Sx + py*Sy) + Sc, exact in int32.
        const int   sq_i = BATCH * (px * px + py * py) - 2 * (px * Sx + py * Sy) + Sc;
        const float sq   = (float)sq_i;
        const float y    = __expf(-sq * 0.2f);   // underflows to 0 exactly like fp32 ref
        const float d    = y_hat - y;
        float term;
        if (y == 1.0f) {
            term = -__logf(y_hat) * d * d;
        } else {
            const float omy = 1.0f - y;
            const float w2  = omy * omy;
            term = -__logf(1.0f - y_hat) * (w2 * w2) * d * d;
        }
        if (valid) fpsum += __float2int_rn(term * FP_SCALE);   // term >= 0
    }

    // Exact, order-independent warp reduction.
    fpsum = __reduce_add_sync(0xFFFFFFFFu, fpsum);

    if (t == 0) {
        const unsigned long long mine =
            (1ULL << 54) | ((unsigned long long)(unsigned int)fpsum << 14)
                         | (unsigned long long)cnt;
        const unsigned long long old = atomicAdd(&gPack, mine);
        if ((old >> 54) == (unsigned long long)(BATCH - 1)) {
            // All 255 other adds are complete at the LTS (their arrivals are in `old`),
            // and same-thread same-address ordering holds, so a plain store reset is safe
            // and avoids the ATOMG.EXCH round-trip on the retire path.
            *(volatile unsigned long long*)&gPack = 0ULL;

            const unsigned long long tot = old + mine;   // complete total, no readback
            const long long fp = (long long)((tot >> 14) & ((1ULL << 40) - 1));
            const int       c  = (int)(tot & 0x3FFFULL);
            // fp <= ~5.5e9 -> fp32 rel err ~6e-8; keeps fp64 off the retire path.
            out[0] = (float)fp * (1.0f / FP_SCALE) / (float)c;
        }
    }
}

extern "C" void kernel_launch(void* const* d_in, const int* in_sizes, int n_in,
                              void* d_out, int out_size) {
    const float* y_predict = (const float*)d_in[0];
    const int*   gt_pos    = (const int*)d_in[1];
    float*       out       = (float*)d_out;
    loss_39934605918651_kernel<<<BATCH, 32>>>(y_predict, gt_pos, out);
}